// round 17
// baseline (speedup 1.0000x reference)
#include <cuda_runtime.h>
#include <cuda_bf16.h>
#include <cstddef>
#include <cstdint>

// B=16, N=512, T=24, F=64, BT=384
#define T_DIM 24
#define N_DIM 512
#define BT_DIM 384

// Scratch (device globals: allocation-free per harness rules)
static __device__ float g_EE[N_DIM * N_DIM];                                 // 1 MB, emb@emb^T
static __device__ float g_ED[N_DIM];                                         // ||emb_n||^2
static __device__ float g_D[(size_t)BT_DIM * N_DIM];                         // diag shift
static __device__ __nv_bfloat16 g_Xhi[(size_t)BT_DIM * N_DIM * 64];          // 25 MB
static __device__ __nv_bfloat16 g_Xlo[(size_t)BT_DIM * N_DIM * 64];          // 25 MB
static __device__ __nv_bfloat16 g_Vhi[(size_t)BT_DIM * 128 * N_DIM];         // 50 MB
static __device__ __nv_bfloat16 g_Vlo[(size_t)BT_DIM * 128 * N_DIM];         // 50 MB

typedef unsigned long long u64;
__device__ __forceinline__ u64 pack2(float lo, float hi) {
    u64 r; asm("mov.b64 %0, {%1, %2};" : "=l"(r) : "f"(lo), "f"(hi)); return r;
}
__device__ __forceinline__ u64 ffma2(u64 a, u64 b, u64 c) {
    u64 d; asm("fma.rn.f32x2 %0, %1, %2, %3;" : "=l"(d) : "l"(a), "l"(b), "l"(c)); return d;
}
__device__ __forceinline__ float2 unpack2(u64 v) {
    float2 r; asm("mov.b64 {%0, %1}, %2;" : "=f"(r.x), "=f"(r.y) : "l"(v)); return r;
}

// ---- warp-level tensor core plumbing (sm_80 baseline PTX) ------------------
__device__ __forceinline__ uint32_t smem_u32(const void* p) {
    uint32_t a;
    asm("{ .reg .u64 t; cvta.to.shared.u64 t, %1; cvt.u32.u64 %0, t; }" : "=r"(a) : "l"(p));
    return a;
}
__device__ __forceinline__ void ldm4(uint32_t addr, uint32_t* r) {
    asm volatile("ldmatrix.sync.aligned.m8n8.x4.shared.b16 {%0,%1,%2,%3}, [%4];"
                 : "=r"(r[0]), "=r"(r[1]), "=r"(r[2]), "=r"(r[3]) : "r"(addr));
}
__device__ __forceinline__ void mma16816(float* d, const uint32_t* a, const uint32_t* b) {
    asm volatile("mma.sync.aligned.m16n8k16.row.col.f32.bf16.bf16.f32 "
        "{%0,%1,%2,%3}, {%4,%5,%6,%7}, {%8,%9}, {%0,%1,%2,%3};"
        : "+f"(d[0]), "+f"(d[1]), "+f"(d[2]), "+f"(d[3])
        : "r"(a[0]), "r"(a[1]), "r"(a[2]), "r"(a[3]), "r"(b[0]), "r"(b[1]));
}
// SW128 swizzle for 128B-pitch tiles
__device__ __forceinline__ uint32_t swadr(uint32_t base, int row, int colb) {
    uint32_t off = row * 128 + colb;
    return base + (off ^ ((off >> 3) & 0x70));
}
#define CP_COMMIT() asm volatile("cp.async.commit_group;" ::: "memory")
template <int N>
__device__ __forceinline__ void cp_wait() {
    asm volatile("cp.async.wait_group %0;" :: "n"(N) : "memory");
}

// ---------------------------------------------------------------------------
// k_ee: EE = emb @ emb^T (512x512, K=64) in fp32; diag -> g_ED.
// ---------------------------------------------------------------------------
__global__ void k_ee(const float* __restrict__ emb) {
    __shared__ float As[64][68];
    __shared__ float Bs[64][65];
    const int rb = blockIdx.y * 64, cb = blockIdx.x * 64;
    const int tid = threadIdx.x;
    #pragma unroll
    for (int it = 0; it < 4; ++it) {
        int i = tid + it * 256;
        int r = i >> 4, k4 = i & 15;
        float4 a = *(const float4*)(emb + (rb + r) * 64 + k4 * 4);
        *(float4*)(&As[r][k4 * 4]) = a;
        float4 w = *(const float4*)(emb + (cb + r) * 64 + k4 * 4);
        Bs[k4 * 4 + 0][r] = w.x; Bs[k4 * 4 + 1][r] = w.y;
        Bs[k4 * 4 + 2][r] = w.z; Bs[k4 * 4 + 3][r] = w.w;
    }
    __syncthreads();
    const int ty = tid >> 4, tx = tid & 15;
    float acc[4][4] = {};
    #pragma unroll 8
    for (int k = 0; k < 64; ++k) {
        float a[4], b[4];
        #pragma unroll
        for (int i = 0; i < 4; ++i) a[i] = As[ty * 4 + i][k];
        #pragma unroll
        for (int j = 0; j < 4; ++j) b[j] = Bs[k][tx + 16 * j];
        #pragma unroll
        for (int i = 0; i < 4; ++i)
            #pragma unroll
            for (int j = 0; j < 4; ++j) acc[i][j] = fmaf(a[i], b[j], acc[i][j]);
    }
    #pragma unroll
    for (int i = 0; i < 4; ++i)
        #pragma unroll
        for (int j = 0; j < 4; ++j) {
            int r = rb + ty * 4 + i, c = cb + tx + 16 * j;
            g_EE[r * N_DIM + c] = acc[i][j];
            if (r == c) g_ED[r] = acc[i][j];
        }
}

// ---------------------------------------------------------------------------
// k_prepvw: merged k_prep + k_vwt. Per (bt, 128-row slab):
//   - load X,U slabs to smem (f-major)
//   - X: hi/lo bf16 split -> g_Xhi/lo;  D[bt][n] = ||x||^2 + g_ED[n]
//   - Vt[bt][c][n] = W1 @ X^T (c<64) and W1 @ U^T (c>=64), bf16 hi/lo out
// Reads ori+unc exactly once (saves 200MB vs separate kernels).
// ---------------------------------------------------------------------------
#define VWP 130
#define SMEM_PV ((64 * 66 + 2 * 64 * VWP) * 4)   // 83456 B
__global__ __launch_bounds__(256, 2) void k_prepvw(const float* __restrict__ ori,
                                                   const float* __restrict__ unc,
                                                   const float* __restrict__ W1) {
    extern __shared__ float sm[];
    float (*Ws)[66]  = (float(*)[66])sm;                       // (f, c) 64x66
    float (*Xs)[VWP] = (float(*)[VWP])(sm + 64 * 66);          // (f, n) 64x130
    float (*Us)[VWP] = (float(*)[VWP])(sm + 64 * 66 + 64 * VWP);
    const int nc = blockIdx.x, bt = blockIdx.y;
    const int n0 = nc * 128;
    const int b = bt / T_DIM, t = bt % T_DIM;
    const int tid = threadIdx.x;
    const size_t base = (size_t)b * 786432 + (size_t)t * 64;

    #pragma unroll
    for (int it = 0; it < 4; ++it) {
        int i = tid + it * 256;
        int o = i >> 4, q = i & 15;
        float4 w = *(const float4*)(W1 + o * 64 + q * 4);
        Ws[q * 4 + 0][o] = w.x; Ws[q * 4 + 1][o] = w.y;
        Ws[q * 4 + 2][o] = w.z; Ws[q * 4 + 3][o] = w.w;
    }
    #pragma unroll
    for (int it = 0; it < 8; ++it) {
        int i = tid + it * 256;
        int r = i >> 4, q = i & 15;
        size_t g = base + (size_t)(n0 + r) * 1536 + q * 4;
        float4 v = *(const float4*)(ori + g);
        Xs[q * 4 + 0][r] = v.x; Xs[q * 4 + 1][r] = v.y;
        Xs[q * 4 + 2][r] = v.z; Xs[q * 4 + 3][r] = v.w;
        float4 u = *(const float4*)(unc + g);
        Us[q * 4 + 0][r] = u.x; Us[q * 4 + 1][r] = u.y;
        Us[q * 4 + 2][r] = u.z; Us[q * 4 + 3][r] = u.w;
    }
    __syncthreads();

    // ---- phase B: X hi/lo split + D ----
    {
        const int rl = tid >> 1, hq = tid & 1;
        const int n = n0 + rl, f0 = hq * 32;
        float ss = 0.0f;
        __align__(16) __nv_bfloat16 hb[32], lb[32];
        #pragma unroll
        for (int jf = 0; jf < 32; ++jf) {
            float v = Xs[f0 + jf][rl];
            ss += v * v;
            __nv_bfloat16 h = __float2bfloat16(v);
            hb[jf] = h;
            lb[jf] = __float2bfloat16(v - __bfloat162float(h));
        }
        size_t xo = ((size_t)bt * N_DIM + n) * 64 + f0;
        #pragma unroll
        for (int j = 0; j < 4; ++j) {
            ((uint4*)(g_Xhi + xo))[j] = ((uint4*)hb)[j];
            ((uint4*)(g_Xlo + xo))[j] = ((uint4*)lb)[j];
        }
        float sso = __shfl_xor_sync(0xffffffffu, ss, 1);
        if (hq == 0)
            g_D[(size_t)bt * N_DIM + n] = ss + sso + g_ED[n];
    }

    // ---- phase C: V = W @ [X|U]^T, transposed bf16 hi/lo out ----
    const int ty = tid >> 4, tx = tid & 15;
    #pragma unroll
    for (int hh = 0; hh < 2; ++hh) {
        float (*Bs)[VWP] = hh ? Us : Xs;
        u64 acc[4][4] = {};
        #pragma unroll 8
        for (int k = 0; k < 64; ++k) {
            u64 bp[4];
            #pragma unroll
            for (int j = 0; j < 4; ++j) bp[j] = *(const u64*)(&Bs[k][2 * tx + 32 * j]);
            #pragma unroll
            for (int i2 = 0; i2 < 4; ++i2) {
                float a = Ws[k][ty * 4 + i2];
                u64 ad = pack2(a, a);
                #pragma unroll
                for (int j = 0; j < 4; ++j) acc[i2][j] = ffma2(ad, bp[j], acc[i2][j]);
            }
        }
        #pragma unroll
        for (int i2 = 0; i2 < 4; ++i2) {
            size_t row = (size_t)bt * 128 + hh * 64 + ty * 4 + i2;
            #pragma unroll
            for (int j = 0; j < 4; ++j) {
                float2 v = unpack2(acc[i2][j]);
                __nv_bfloat16 hx = __float2bfloat16(v.x), hy = __float2bfloat16(v.y);
                __nv_bfloat162 h2; h2.x = hx; h2.y = hy;
                __nv_bfloat162 l2;
                l2.x = __float2bfloat16(v.x - __bfloat162float(hx));
                l2.y = __float2bfloat16(v.y - __bfloat162float(hy));
                int n = n0 + 2 * tx + 32 * j;
                *(__nv_bfloat162*)(g_Vhi + row * N_DIM + n) = h2;
                *(__nv_bfloat162*)(g_Vlo + row * N_DIM + n) = l2;
            }
        }
    }
}

// ---------------------------------------------------------------------------
// k_fused: 64-row CTA tile, 8 chunks of 64 cols; 2 CTAs/SM.
//   GEMM1 (X@X^T chunk, K=64, 3-split) -> +EE(smem, cp.async) -> exp(relu-D) ->
//   P(bf16 hi/lo) to smem -> GEMM2 (P @ V chunk, 3-split) accumulating OUT.
// cp.async: double-buffered B; V+EE prefetched during GEMM1.
// smem: A 16K | B 2x16K | P 16K | V 32K | EE 17K = 113K -> 2 CTAs/SM.
// ---------------------------------------------------------------------------
#define SA_HI  0
#define SA_LO  8192
#define SB0    16384
#define SB1    32768
#define SP_HI  49152
#define SP_LO  57344
#define SV     65536
#define SEE    98304
#define SMEM_FU 115712

__device__ __forceinline__ void load_tile64_async(char* dst, const __nv_bfloat16* sp,
                                                  int stride, int tid) {
    #pragma unroll
    for (int it = 0; it < 2; ++it) {
        int i = tid + it * 256;
        int row = i >> 3, q = i & 7;
        uint32_t off = (uint32_t)(row * 128 + q * 16);
        off ^= (off >> 3) & 0x70;
        uint32_t d = smem_u32(dst + off);
        asm volatile("cp.async.cg.shared.global [%0], [%1], 16;"
                     :: "r"(d), "l"(__cvta_generic_to_global(sp + (size_t)row * stride + q * 8))
                     : "memory");
    }
}

__global__ __launch_bounds__(256, 2) void k_fused(float* __restrict__ out, size_t uf_off) {
    extern __shared__ char smc[];
    const int rbi = blockIdx.x, bt = blockIdx.y;
    const int rb = rbi * 64;
    const int b = bt / T_DIM, t = bt % T_DIM;
    const int tid = threadIdx.x;
    const int wid = tid >> 5, lane = tid & 31;
    const uint32_t sbase = smem_u32(smc);
    const int wmr = (wid & 1) * 32;          // row group (both GEMMs)
    const int wn1 = (wid >> 1) * 16;         // GEMM1 col group (16 cols)
    const int wn2 = (wid >> 1) * 32;         // GEMM2 ch group (32 ch)
    const int mat = lane >> 3, rl = lane & 7;
    const size_t xb = (size_t)bt * N_DIM * 64;

    // Prologue: A tiles (persistent) + B(0)
    load_tile64_async(smc + SA_HI, g_Xhi + xb + (size_t)rb * 64, 64, tid);
    load_tile64_async(smc + SA_LO, g_Xlo + xb + (size_t)rb * 64, 64, tid);
    load_tile64_async(smc + SB0,        g_Xhi + xb, 64, tid);
    load_tile64_async(smc + SB0 + 8192, g_Xlo + xb, 64, tid);
    CP_COMMIT();
    cp_wait<0>();
    __syncthreads();

    float accO[2][4][4] = {};
    float rsum[2][2] = {};

    for (int cbi = 0; cbi < 8; ++cbi) {
        const int cb = cbi * 64;
        const uint32_t sB = sbase + ((cbi & 1) ? SB1 : SB0);

        // Prefetch V chunk + EE tile (group VE)
        const __nv_bfloat16* vh = g_Vhi + (size_t)bt * 128 * N_DIM + cb;
        const __nv_bfloat16* vl = g_Vlo + (size_t)bt * 128 * N_DIM + cb;
        load_tile64_async(smc + SV,          vh,                     N_DIM, tid);
        load_tile64_async(smc + SV + 8192,   vh + (size_t)64 * N_DIM, N_DIM, tid);
        load_tile64_async(smc + SV + 16384,  vl,                     N_DIM, tid);
        load_tile64_async(smc + SV + 24576,  vl + (size_t)64 * N_DIM, N_DIM, tid);
        #pragma unroll
        for (int it = 0; it < 4; ++it) {
            int i = tid + it * 256;
            int r = i >> 4, g = i & 15;
            uint32_t d = smem_u32(smc + SEE + r * 272 + g * 16);
            const float* src = g_EE + (size_t)(rb + r) * N_DIM + cb + g * 4;
            asm volatile("cp.async.cg.shared.global [%0], [%1], 16;"
                         :: "r"(d), "l"(__cvta_generic_to_global(src)) : "memory");
        }
        CP_COMMIT();

        // ---- GEMM1: X[rb:+64] @ X[cb:+64]^T, K=64 (4 k16, 3-split) ----
        float accE[2][2][4] = {};
        {
            const uint32_t aH = sbase + SA_HI, aL = sbase + SA_LO;
            const uint32_t bH = sB, bL = sB + 8192;
            #pragma unroll
            for (int kk = 0; kk < 4; ++kk) {
                const int kb = kk * 32;
                uint32_t Bh[2][2], Bl[2][2];
                {
                    int nrow = wn1 + (mat >> 1) * 8 + rl;
                    int col = kb + (mat & 1) * 16;
                    uint32_t th[4], tl[4];
                    ldm4(swadr(bH, nrow, col), th);
                    ldm4(swadr(bL, nrow, col), tl);
                    Bh[0][0] = th[0]; Bh[0][1] = th[1];
                    Bh[1][0] = th[2]; Bh[1][1] = th[3];
                    Bl[0][0] = tl[0]; Bl[0][1] = tl[1];
                    Bl[1][0] = tl[2]; Bl[1][1] = tl[3];
                }
                #pragma unroll
                for (int mi = 0; mi < 2; ++mi) {
                    int row = wmr + mi * 16 + (mat & 1) * 8 + rl;
                    int col = kb + (mat >> 1) * 16;
                    uint32_t Ah[4], Al[4];
                    ldm4(swadr(aH, row, col), Ah);
                    ldm4(swadr(aL, row, col), Al);
                    #pragma unroll
                    for (int ni = 0; ni < 2; ++ni) {
                        mma16816(accE[mi][ni], Ah, Bh[ni]);
                        mma16816(accE[mi][ni], Ah, Bl[ni]);
                        mma16816(accE[mi][ni], Al, Bh[ni]);
                    }
                }
            }
        }

        // Prefetch B(c+1) (group B)
        if (cbi < 7) {
            char* nb = smc + ((cbi & 1) ? SB0 : SB1);
            load_tile64_async(nb,        g_Xhi + xb + (size_t)(cb + 64) * 64, 64, tid);
            load_tile64_async(nb + 8192, g_Xlo + xb + (size_t)(cb + 64) * 64, 64, tid);
            CP_COMMIT();
        }

        // V + EE must be resident before epilogue (B(c+1) may stay in flight)
        if (cbi < 7) cp_wait<1>(); else cp_wait<0>();
        __syncthreads();

        // ---- epilogue: +EE (smem), exp(relu-D), rowsum, pack P ----
        #pragma unroll
        for (int mi = 0; mi < 2; ++mi) {
            #pragma unroll
            for (int h = 0; h < 2; ++h) {
                int rloc = wmr + mi * 16 + h * 8 + (lane >> 2);
                int r = rb + rloc;
                float dr = g_D[(size_t)bt * N_DIM + r];
                #pragma unroll
                for (int ni = 0; ni < 2; ++ni) {
                    int n = wn1 + ni * 8 + (lane & 3) * 2;
                    float2 ee = *(const float2*)(smc + SEE + rloc * 272 + n * 4);
                    float p0 = __expf(fmaxf(accE[mi][ni][h * 2 + 0] + ee.x, 0.0f) - dr);
                    float p1 = __expf(fmaxf(accE[mi][ni][h * 2 + 1] + ee.y, 0.0f) - dr);
                    rsum[mi][h] += p0 + p1;
                    __nv_bfloat162 hh, ll;
                    hh.x = __float2bfloat16(p0);
                    hh.y = __float2bfloat16(p1);
                    ll.x = __float2bfloat16(p0 - __bfloat162float(hh.x));
                    ll.y = __float2bfloat16(p1 - __bfloat162float(hh.y));
                    uint32_t off = (uint32_t)(rloc * 128 + n * 2);
                    off ^= (off >> 3) & 0x70;
                    *(__nv_bfloat162*)(smc + SP_HI + off) = hh;
                    *(__nv_bfloat162*)(smc + SP_LO + off) = ll;
                }
            }
        }
        __syncthreads();

        // ---- GEMM2: OUT += P @ V^T (K = 64 chunk cols, 4 k16) ----
        {
            const uint32_t aH = sbase + SP_HI, aL = sbase + SP_LO;
            #pragma unroll
            for (int kk = 0; kk < 4; ++kk) {
                const int kb = kk * 32;
                uint32_t Bh[4][2], Bl[4][2];
                #pragma unroll
                for (int g = 0; g < 2; ++g) {
                    int grp = wn2 + g * 16;
                    int tile = grp >> 6;
                    int nr = (grp & 63) + (mat >> 1) * 8 + rl;
                    int col = kb + (mat & 1) * 16;
                    uint32_t bHt = sbase + SV + tile * 8192;
                    uint32_t bLt = sbase + SV + 16384 + tile * 8192;
                    uint32_t th[4], tl[4];
                    ldm4(swadr(bHt, nr, col), th);
                    ldm4(swadr(bLt, nr, col), tl);
                    Bh[2 * g][0] = th[0]; Bh[2 * g][1] = th[1];
                    Bh[2 * g + 1][0] = th[2]; Bh[2 * g + 1][1] = th[3];
                    Bl[2 * g][0] = tl[0]; Bl[2 * g][1] = tl[1];
                    Bl[2 * g + 1][0] = tl[2]; Bl[2 * g + 1][1] = tl[3];
                }
                #pragma unroll
                for (int mi = 0; mi < 2; ++mi) {
                    int row = wmr + mi * 16 + (mat & 1) * 8 + rl;
                    int col = kb + (mat >> 1) * 16;
                    uint32_t Ah[4], Al[4];
                    ldm4(swadr(aH, row, col), Ah);
                    ldm4(swadr(aL, row, col), Al);
                    #pragma unroll
                    for (int ni = 0; ni < 4; ++ni) {
                        mma16816(accO[mi][ni], Ah, Bh[ni]);
                        mma16816(accO[mi][ni], Ah, Bl[ni]);
                        mma16816(accO[mi][ni], Al, Bh[ni]);
                    }
                }
            }
        }
        cp_wait<0>();
        __syncthreads();
    }

    // ---- rowsum cross-warp reduce (reuse B buffers) ----
    float* rs = (float*)(smc + SB0);  // [4 n-groups][64 rows]
    #pragma unroll
    for (int mi = 0; mi < 2; ++mi) {
        #pragma unroll
        for (int h = 0; h < 2; ++h) {
            float v = rsum[mi][h];
            v += __shfl_xor_sync(0xffffffffu, v, 1);
            v += __shfl_xor_sync(0xffffffffu, v, 2);
            if ((lane & 3) == 0) {
                int rloc = wmr + mi * 16 + h * 8 + (lane >> 2);
                rs[(wid >> 1) * 64 + rloc] = v;
            }
        }
    }
    __syncthreads();

    // ---- final: normalize, relu, scatter ----
    #pragma unroll
    for (int mi = 0; mi < 2; ++mi) {
        #pragma unroll
        for (int h = 0; h < 2; ++h) {
            int rloc = wmr + mi * 16 + h * 8 + (lane >> 2);
            int n = rb + rloc;
            float tot = rs[rloc] + rs[64 + rloc] + rs[128 + rloc] + rs[192 + rloc];
            float inv = 1.0f / tot;
            size_t obase = (size_t)b * 786432 + (size_t)n * 1536 + (size_t)t * 64;
            #pragma unroll
            for (int ni = 0; ni < 4; ++ni) {
                int ch = wn2 + ni * 8 + (lane & 3) * 2;
                float2 v;
                v.x = fmaxf(accO[mi][ni][h * 2 + 0] * inv, 0.0f);
                v.y = fmaxf(accO[mi][ni][h * 2 + 1] * inv, 0.0f);
                if (ch < 64) *(float2*)(out + obase + ch) = v;
                else         *(float2*)(out + uf_off + obase + (ch - 64)) = v;
            }
        }
    }
}

// ---------------------------------------------------------------------------
extern "C" void kernel_launch(void* const* d_in, const int* in_sizes, int n_in,
                              void* d_out, int out_size) {
    const float* ori = (const float*)d_in[0];   // (16,512,24,64)
    const float* unc = (const float*)d_in[1];   // (16,512,24,64)
    const float* emb = (const float*)d_in[2];   // (512,64)
    const float* W1  = (const float*)d_in[3];   // (64,64)
    float* out = (float*)d_out;                 // [of | uf]
    const size_t uf_off = (size_t)out_size / 2;

    cudaFuncSetAttribute(k_prepvw, cudaFuncAttributeMaxDynamicSharedMemorySize, SMEM_PV);
    cudaFuncSetAttribute(k_fused, cudaFuncAttributeMaxDynamicSharedMemorySize, SMEM_FU);

    k_ee<<<dim3(8, 8), 256>>>(emb);
    k_prepvw<<<dim3(4, BT_DIM), 256, SMEM_PV>>>(ori, unc, W1);
    k_fused<<<dim3(8, BT_DIM), 256, SMEM_FU>>>(out, uf_off);
}